// round 14
// baseline (speedup 1.0000x reference)
#include <cuda_runtime.h>
#include <cuda_fp16.h>
#include <cstdint>

#define NN 50000
#define F  256
#define KW 3

// Scratch (no cudaMalloc allowed).
__device__ __half g_xh[(size_t)NN * F];
__device__ __half g_T1[(size_t)NN * F];
__device__ __half g_T2[(size_t)NN * F];      // U = L @ T1 (weights folded)
__device__ __half g_wh[(size_t)KW * F * F];  // folded: [W0-W2 | W1 | 2*W2]
__device__ int    g_rp[NN + 1];

// ---------------------------------------------------------------------------
// Prep (R13 version): x->fp16 (4 float4/thread), folded weights->fp16, row_ptr.
// ---------------------------------------------------------------------------
__global__ void prep_kernel(const float* __restrict__ x,
                            const float* __restrict__ wgt,
                            const int* __restrict__ erow,
                            int E, int N, int XB, int WB) {
    int b = blockIdx.x;
    if (b < XB + WB) {
        bool isx = (b < XB);
        int base4 = ((isx ? b : b - XB) * 256 + threadIdx.x) * 4;
        int n4 = isx ? N * F / 4 : KW * F * F / 4;
        const float* src = isx ? x : wgt;
        __half* dst = isx ? g_xh : g_wh;
        #pragma unroll
        for (int u = 0; u < 4; ++u) {
            int i = base4 + u;
            if (i >= n4) break;
            float4 v = *reinterpret_cast<const float4*>(src + (size_t)i * 4);
            if (!isx) {
                int k = i / (F * F / 4);
                if (k == 0) {
                    float4 w2 = *reinterpret_cast<const float4*>(
                        wgt + (size_t)(i + 2 * (F * F / 4)) * 4);
                    v.x -= w2.x; v.y -= w2.y; v.z -= w2.z; v.w -= w2.w;
                } else if (k == 2) {
                    v.x *= 2.f; v.y *= 2.f; v.z *= 2.f; v.w *= 2.f;
                }
            }
            __half2 h0 = __floats2half2_rn(v.x, v.y);
            __half2 h1 = __floats2half2_rn(v.z, v.w);
            uint2 o;
            o.x = *reinterpret_cast<uint32_t*>(&h0);
            o.y = *reinterpret_cast<uint32_t*>(&h1);
            *reinterpret_cast<uint2*>(dst + (size_t)i * 4) = o;
        }
    } else {
        int i = (b - XB - WB) * 256 + threadIdx.x;
        if (i > N) return;
        int lo = 0, hi = E;
        while (lo < hi) {
            int mid = (lo + hi) >> 1;
            if (erow[mid] < i) lo = mid + 1; else hi = mid;
        }
        g_rp[i] = lo;
    }
}

// ---------------------------------------------------------------------------
// SpMM (R2 structure; byte-capped at the LTS gather ceiling — untouched).
// MODE 0: T1 = L xh     MODE 1: U = L T1
// ---------------------------------------------------------------------------
__device__ __forceinline__ void accum8(float acc[8], uint4 v, float w) {
    const __half2* h = reinterpret_cast<const __half2*>(&v);
    #pragma unroll
    for (int q = 0; q < 4; ++q) {
        float2 f = __half22float2(h[q]);
        acc[2 * q]     = fmaf(w, f.x, acc[2 * q]);
        acc[2 * q + 1] = fmaf(w, f.y, acc[2 * q + 1]);
    }
}

template <int MODE>
__global__ __launch_bounds__(256)
void spmm_h_kernel(const int* __restrict__ ecol, const float* __restrict__ ew) {
    int warp = threadIdx.x >> 5, lane = threadIdx.x & 31;
    int node = blockIdx.x * 8 + warp;
    if (node >= NN) return;

    const uint4* __restrict__ src =
        reinterpret_cast<const uint4*>((MODE == 0) ? g_xh : g_T1);
    __half* dst = (MODE == 0) ? g_T1 : g_T2;

    int r0 = g_rp[node], r1 = g_rp[node + 1];
    float acc[8];
    #pragma unroll
    for (int q = 0; q < 8; ++q) acc[q] = 0.f;

    for (int base = r0; base < r1; base += 32) {
        int cnt = min(32, r1 - base);
        int   c  = 0;
        float wv = 0.f;
        if (base + lane < r1) {
            c  = ecol[base + lane];
            wv = ew[base + lane];
        }
        int j = 0;
        for (; j + 4 <= cnt; j += 4) {
            int   c0 = __shfl_sync(0xffffffffu, c,  j);
            int   c1 = __shfl_sync(0xffffffffu, c,  j + 1);
            int   c2 = __shfl_sync(0xffffffffu, c,  j + 2);
            int   c3 = __shfl_sync(0xffffffffu, c,  j + 3);
            float w0 = __shfl_sync(0xffffffffu, wv, j);
            float w1 = __shfl_sync(0xffffffffu, wv, j + 1);
            float w2 = __shfl_sync(0xffffffffu, wv, j + 2);
            float w3 = __shfl_sync(0xffffffffu, wv, j + 3);
            uint4 v0 = __ldg(&src[(size_t)c0 * 32 + lane]);
            uint4 v1 = __ldg(&src[(size_t)c1 * 32 + lane]);
            uint4 v2 = __ldg(&src[(size_t)c2 * 32 + lane]);
            uint4 v3 = __ldg(&src[(size_t)c3 * 32 + lane]);
            accum8(acc, v0, w0);
            accum8(acc, v1, w1);
            accum8(acc, v2, w2);
            accum8(acc, v3, w3);
        }
        for (; j < cnt; ++j) {
            int   cj = __shfl_sync(0xffffffffu, c,  j);
            float wj = __shfl_sync(0xffffffffu, wv, j);
            uint4 v = __ldg(&src[(size_t)cj * 32 + lane]);
            accum8(acc, v, wj);
        }
    }

    __half2 o[4];
    #pragma unroll
    for (int q = 0; q < 4; ++q) o[q] = __floats2half2_rn(acc[2 * q], acc[2 * q + 1]);
    reinterpret_cast<uint4*>(dst)[(size_t)node * 32 + lane] =
        *reinterpret_cast<uint4*>(o);
}

// ---------------------------------------------------------------------------
// GEMM (R11 version, best measured: 62us): out = [xh|T1|U] @ Wf + bias
// BM=128 BN=64 BK=64, 256 thr (8 warps: 4M x 2N), 3-stage cp.async,
// SW128-swizzled smem, one barrier per iter, grid (4, 391).
// ---------------------------------------------------------------------------
#define GBM 128
#define GBN 64
#define GBK 64
#define ASTG_B 16384u
#define BSTG_B 8192u
#define STG_B  (ASTG_B + BSTG_B)
#define NITER  12

#define SWZ(x) ((x) ^ (((x) >> 3) & 0x70u))

__device__ __forceinline__ void cp16(uint32_t dst, const void* src, int sz) {
    asm volatile("cp.async.cg.shared.global [%0], [%1], 16, %2;\n"
                 :: "r"(dst), "l"(src), "r"(sz));
}
__device__ __forceinline__ void ldsm_x4(uint32_t r[4], uint32_t addr) {
    asm volatile("ldmatrix.sync.aligned.m8n8.x4.shared.b16 {%0,%1,%2,%3}, [%4];"
                 : "=r"(r[0]), "=r"(r[1]), "=r"(r[2]), "=r"(r[3]) : "r"(addr));
}
__device__ __forceinline__ void ldsm_x4_t(uint32_t r[4], uint32_t addr) {
    asm volatile("ldmatrix.sync.aligned.m8n8.x4.trans.shared.b16 {%0,%1,%2,%3}, [%4];"
                 : "=r"(r[0]), "=r"(r[1]), "=r"(r[2]), "=r"(r[3]) : "r"(addr));
}

__global__ __launch_bounds__(256)
void gemm_h_kernel(const float* __restrict__ bias, float* __restrict__ out, int N) {
    extern __shared__ __half sm[];

    int tid  = threadIdx.x;
    int warp = tid >> 5, lane = tid & 31;
    int col0 = blockIdx.x * GBN;
    int row0 = blockIdx.y * GBM;
    int wm = (warp >> 1) * 32;
    int wn = (warp & 1) * 32;

    float acc[2][4][4];
    #pragma unroll
    for (int mi = 0; mi < 2; ++mi)
        #pragma unroll
        for (int ni = 0; ni < 4; ++ni)
            #pragma unroll
            for (int q = 0; q < 4; ++q) acc[mi][ni][q] = 0.f;

    uint32_t base = (uint32_t)__cvta_generic_to_shared(sm);

    auto issue = [&](int s, int iter) {
        const __half* asrc = (iter < 4) ? g_xh : (iter < 8) ? g_T1 : g_T2;
        int colA = (iter & 3) * GBK;
        uint32_t aS = base + (uint32_t)s * STG_B;
        uint32_t bS = aS + ASTG_B;
        #pragma unroll
        for (int it = 0; it < 4; ++it) {
            int idx = tid + it * 256;
            int r = idx >> 3, c = idx & 7;
            int grow = row0 + r;
            const __half* g = asrc + (size_t)min(grow, NN - 1) * 256 + colA + c * 8;
            cp16(aS + SWZ((uint32_t)(r * 128 + c * 16)), g, grow < N ? 16 : 0);
        }
        int kb = iter * GBK;
        #pragma unroll
        for (int it = 0; it < 2; ++it) {
            int idx = tid + it * 256;
            int r = idx >> 3, c = idx & 7;
            const __half* g = g_wh + (size_t)(kb + r) * 256 + col0 + c * 8;
            cp16(bS + SWZ((uint32_t)(r * 128 + c * 16)), g, 16);
        }
    };

    issue(0, 0);
    asm volatile("cp.async.commit_group;");
    issue(1, 1);
    asm volatile("cp.async.commit_group;");

    int s = 0;
    for (int iter = 0; iter < NITER; ++iter) {
        asm volatile("cp.async.wait_group 1;");
        __syncthreads();

        if (iter + 2 < NITER) {
            int sn = (s + 2 >= 3) ? s - 1 : s + 2;
            issue(sn, iter + 2);
        }
        asm volatile("cp.async.commit_group;");

        uint32_t aS = base + (uint32_t)s * STG_B;
        uint32_t bS = aS + ASTG_B;
        #pragma unroll
        for (int kc = 0; kc < 4; ++kc) {
            uint32_t a[2][4], b[2][4];
            #pragma unroll
            for (int mi = 0; mi < 2; ++mi) {
                uint32_t off = (uint32_t)((wm + mi * 16 + (lane & 15)) * 128
                                          + kc * 32 + (lane >> 4) * 16);
                ldsm_x4(a[mi], aS + SWZ(off));
            }
            #pragma unroll
            for (int bi = 0; bi < 2; ++bi) {
                uint32_t off = (uint32_t)((kc * 16 + (lane & 15)) * 128
                                          + wn * 2 + bi * 32 + (lane >> 4) * 16);
                ldsm_x4_t(b[bi], bS + SWZ(off));
            }
            #pragma unroll
            for (int mi = 0; mi < 2; ++mi)
                #pragma unroll
                for (int ni = 0; ni < 4; ++ni) {
                    uint32_t b0 = b[ni >> 1][(ni & 1) * 2];
                    uint32_t b1 = b[ni >> 1][(ni & 1) * 2 + 1];
                    asm volatile(
                        "mma.sync.aligned.m16n8k16.row.col.f32.f16.f16.f32 "
                        "{%0,%1,%2,%3}, {%4,%5,%6,%7}, {%8,%9}, {%0,%1,%2,%3};"
                        : "+f"(acc[mi][ni][0]), "+f"(acc[mi][ni][1]),
                          "+f"(acc[mi][ni][2]), "+f"(acc[mi][ni][3])
                        : "r"(a[mi][0]), "r"(a[mi][1]), "r"(a[mi][2]), "r"(a[mi][3]),
                          "r"(b0), "r"(b1));
                }
        }
        s = (s + 1 >= 3) ? 0 : s + 1;
    }

    int g = lane >> 2, t = lane & 3;
    #pragma unroll
    for (int ni = 0; ni < 4; ++ni) {
        int col = col0 + wn + ni * 8 + t * 2;
        float b0 = __ldg(bias + col), b1 = __ldg(bias + col + 1);
        #pragma unroll
        for (int mi = 0; mi < 2; ++mi) {
            int row = row0 + wm + mi * 16 + g;
            if (row < N) {
                float2 v = make_float2(acc[mi][ni][0] + b0, acc[mi][ni][1] + b1);
                *reinterpret_cast<float2*>(out + (size_t)row * 256 + col) = v;
            }
            if (row + 8 < N) {
                float2 v = make_float2(acc[mi][ni][2] + b0, acc[mi][ni][3] + b1);
                *reinterpret_cast<float2*>(out + (size_t)(row + 8) * 256 + col) = v;
            }
        }
    }
}

// ---------------------------------------------------------------------------
extern "C" void kernel_launch(void* const* d_in, const int* in_sizes, int n_in,
                              void* d_out, int out_size) {
    const float* x    = (const float*)d_in[0];
    const int*   erow = (const int*)  d_in[1];
    const int*   ecol = (const int*)  d_in[2];
    const float* ew   = (const float*)d_in[3];
    const float* wgt  = (const float*)d_in[4];
    const float* bias = (const float*)d_in[5];
    float* out = (float*)d_out;

    int N = in_sizes[0] / F;   // 50000
    int E = in_sizes[1];       // 1600000

    static int once = 0;
    if (!once) {
        cudaFuncSetAttribute(gemm_h_kernel,
                             cudaFuncAttributeMaxDynamicSharedMemorySize,
                             3 * STG_B);
        once = 1;
    }

    int XB = (N * F / 4 + 1023) / 1024;          // 782 (4 float4/thread)
    int WB = (KW * F * F / 4 + 1023) / 1024;     // 48
    int RB = (N + 1 + 255) / 256;                // 196
    prep_kernel<<<XB + WB + RB, 256>>>(x, wgt, erow, E, N, XB, WB);

    spmm_h_kernel<0><<<(N + 7) / 8, 256>>>(ecol, ew);   // T1 = L xh
    spmm_h_kernel<1><<<(N + 7) / 8, 256>>>(ecol, ew);   // U  = L T1

    dim3 grid(F / GBN, (N + GBM - 1) / GBM);            // (4, 391)
    gemm_h_kernel<<<grid, 256, 3 * STG_B>>>(bias, out, N);
}

// round 15
// speedup vs baseline: 1.0082x; 1.0082x over previous
#include <cuda_runtime.h>
#include <cuda_fp16.h>
#include <cstdint>

#define NN 50000
#define F  256
#define KW 3

// Scratch (no cudaMalloc allowed).
__device__ __half g_xh[(size_t)NN * F];
__device__ __half g_T1[(size_t)NN * F];
__device__ __half g_T2[(size_t)NN * F];      // U = L @ T1 (weights folded)
__device__ __half g_wh[(size_t)KW * F * F];  // folded: [W0-W2 | W1 | 2*W2]
__device__ int    g_rp[NN + 1];

// ---------------------------------------------------------------------------
// Prep: x->fp16 (4 float4/thread), folded weights->fp16, row_ptr.
// ---------------------------------------------------------------------------
__global__ void prep_kernel(const float* __restrict__ x,
                            const float* __restrict__ wgt,
                            const int* __restrict__ erow,
                            int E, int N, int XB, int WB) {
    int b = blockIdx.x;
    if (b < XB + WB) {
        bool isx = (b < XB);
        int base4 = ((isx ? b : b - XB) * 256 + threadIdx.x) * 4;
        int n4 = isx ? N * F / 4 : KW * F * F / 4;
        const float* src = isx ? x : wgt;
        __half* dst = isx ? g_xh : g_wh;
        #pragma unroll
        for (int u = 0; u < 4; ++u) {
            int i = base4 + u;
            if (i >= n4) break;
            float4 v = *reinterpret_cast<const float4*>(src + (size_t)i * 4);
            if (!isx) {
                int k = i / (F * F / 4);
                if (k == 0) {
                    float4 w2 = *reinterpret_cast<const float4*>(
                        wgt + (size_t)(i + 2 * (F * F / 4)) * 4);
                    v.x -= w2.x; v.y -= w2.y; v.z -= w2.z; v.w -= w2.w;
                } else if (k == 2) {
                    v.x *= 2.f; v.y *= 2.f; v.z *= 2.f; v.w *= 2.f;
                }
            }
            __half2 h0 = __floats2half2_rn(v.x, v.y);
            __half2 h1 = __floats2half2_rn(v.z, v.w);
            uint2 o;
            o.x = *reinterpret_cast<uint32_t*>(&h0);
            o.y = *reinterpret_cast<uint32_t*>(&h1);
            *reinterpret_cast<uint2*>(dst + (size_t)i * 4) = o;
        }
    } else {
        int i = (b - XB - WB) * 256 + threadIdx.x;
        if (i > N) return;
        int lo = 0, hi = E;
        while (lo < hi) {
            int mid = (lo + hi) >> 1;
            if (erow[mid] < i) lo = mid + 1; else hi = mid;
        }
        g_rp[i] = lo;
    }
}

// ---------------------------------------------------------------------------
// SpMM (byte-capped at the LTS gather ceiling — untouched).
// MODE 0: T1 = L xh     MODE 1: U = L T1
// ---------------------------------------------------------------------------
__device__ __forceinline__ void accum8(float acc[8], uint4 v, float w) {
    const __half2* h = reinterpret_cast<const __half2*>(&v);
    #pragma unroll
    for (int q = 0; q < 4; ++q) {
        float2 f = __half22float2(h[q]);
        acc[2 * q]     = fmaf(w, f.x, acc[2 * q]);
        acc[2 * q + 1] = fmaf(w, f.y, acc[2 * q + 1]);
    }
}

template <int MODE>
__global__ __launch_bounds__(256)
void spmm_h_kernel(const int* __restrict__ ecol, const float* __restrict__ ew) {
    int warp = threadIdx.x >> 5, lane = threadIdx.x & 31;
    int node = blockIdx.x * 8 + warp;
    if (node >= NN) return;

    const uint4* __restrict__ src =
        reinterpret_cast<const uint4*>((MODE == 0) ? g_xh : g_T1);
    __half* dst = (MODE == 0) ? g_T1 : g_T2;

    int r0 = g_rp[node], r1 = g_rp[node + 1];
    float acc[8];
    #pragma unroll
    for (int q = 0; q < 8; ++q) acc[q] = 0.f;

    for (int base = r0; base < r1; base += 32) {
        int cnt = min(32, r1 - base);
        int   c  = 0;
        float wv = 0.f;
        if (base + lane < r1) {
            c  = ecol[base + lane];
            wv = ew[base + lane];
        }
        int j = 0;
        for (; j + 4 <= cnt; j += 4) {
            int   c0 = __shfl_sync(0xffffffffu, c,  j);
            int   c1 = __shfl_sync(0xffffffffu, c,  j + 1);
            int   c2 = __shfl_sync(0xffffffffu, c,  j + 2);
            int   c3 = __shfl_sync(0xffffffffu, c,  j + 3);
            float w0 = __shfl_sync(0xffffffffu, wv, j);
            float w1 = __shfl_sync(0xffffffffu, wv, j + 1);
            float w2 = __shfl_sync(0xffffffffu, wv, j + 2);
            float w3 = __shfl_sync(0xffffffffu, wv, j + 3);
            uint4 v0 = __ldg(&src[(size_t)c0 * 32 + lane]);
            uint4 v1 = __ldg(&src[(size_t)c1 * 32 + lane]);
            uint4 v2 = __ldg(&src[(size_t)c2 * 32 + lane]);
            uint4 v3 = __ldg(&src[(size_t)c3 * 32 + lane]);
            accum8(acc, v0, w0);
            accum8(acc, v1, w1);
            accum8(acc, v2, w2);
            accum8(acc, v3, w3);
        }
        for (; j < cnt; ++j) {
            int   cj = __shfl_sync(0xffffffffu, c,  j);
            float wj = __shfl_sync(0xffffffffu, wv, j);
            uint4 v = __ldg(&src[(size_t)cj * 32 + lane]);
            accum8(acc, v, wj);
        }
    }

    __half2 o[4];
    #pragma unroll
    for (int q = 0; q < 4; ++q) o[q] = __floats2half2_rn(acc[2 * q], acc[2 * q + 1]);
    reinterpret_cast<uint4*>(dst)[(size_t)node * 32 + lane] =
        *reinterpret_cast<uint4*>(o);
}

// ---------------------------------------------------------------------------
// GEMM (R11 best-measured shape): out = [xh|T1|U] @ Wf + bias
// BM=128 BN=64 BK=64, 256 thr (8 warps: 4M x 2N), 3-stage cp.async,
// SW128-swizzled smem, one barrier per iter, grid (4, 391).
// Micro: clamped A base pointer hoisted; bias loads hoisted out of epilogue.
// ---------------------------------------------------------------------------
#define GBM 128
#define GBN 64
#define GBK 64
#define ASTG_B 16384u
#define BSTG_B 8192u
#define STG_B  (ASTG_B + BSTG_B)
#define NITER  12

#define SWZ(x) ((x) ^ (((x) >> 3) & 0x70u))

__device__ __forceinline__ void cp16(uint32_t dst, const void* src, int sz) {
    asm volatile("cp.async.cg.shared.global [%0], [%1], 16, %2;\n"
                 :: "r"(dst), "l"(src), "r"(sz));
}
__device__ __forceinline__ void ldsm_x4(uint32_t r[4], uint32_t addr) {
    asm volatile("ldmatrix.sync.aligned.m8n8.x4.shared.b16 {%0,%1,%2,%3}, [%4];"
                 : "=r"(r[0]), "=r"(r[1]), "=r"(r[2]), "=r"(r[3]) : "r"(addr));
}
__device__ __forceinline__ void ldsm_x4_t(uint32_t r[4], uint32_t addr) {
    asm volatile("ldmatrix.sync.aligned.m8n8.x4.trans.shared.b16 {%0,%1,%2,%3}, [%4];"
                 : "=r"(r[0]), "=r"(r[1]), "=r"(r[2]), "=r"(r[3]) : "r"(addr));
}

__global__ __launch_bounds__(256)
void gemm_h_kernel(const float* __restrict__ bias, float* __restrict__ out, int N) {
    extern __shared__ __half sm[];

    int tid  = threadIdx.x;
    int warp = tid >> 5, lane = tid & 31;
    int col0 = blockIdx.x * GBN;
    int row0 = blockIdx.y * GBM;
    int wm = (warp >> 1) * 32;
    int wn = (warp & 1) * 32;

    float acc[2][4][4];
    #pragma unroll
    for (int mi = 0; mi < 2; ++mi)
        #pragma unroll
        for (int ni = 0; ni < 4; ++ni)
            #pragma unroll
            for (int q = 0; q < 4; ++q) acc[mi][ni][q] = 0.f;

    uint32_t base = (uint32_t)__cvta_generic_to_shared(sm);

    // Per-thread staging coords (constant across iters).
    int ra = tid >> 3, ca = tid & 7;          // A: 4 chunks/thread via +32 rows
    int rb = tid >> 3, cb = tid & 7;          // B: 2 chunks/thread via +32 rows

    auto issue = [&](int s, int iter) {
        const __half* asrc = (iter < 4) ? g_xh : (iter < 8) ? g_T1 : g_T2;
        int colA = (iter & 3) * GBK;
        uint32_t aS = base + (uint32_t)s * STG_B;
        uint32_t bS = aS + ASTG_B;
        #pragma unroll
        for (int it = 0; it < 4; ++it) {
            int r = ra + it * 32;
            int grow = row0 + r;
            const __half* g = asrc + (size_t)min(grow, NN - 1) * 256 + colA + ca * 8;
            cp16(aS + SWZ((uint32_t)(r * 128 + ca * 16)), g, grow < N ? 16 : 0);
        }
        int kb = iter * GBK;
        #pragma unroll
        for (int it = 0; it < 2; ++it) {
            int r = rb + it * 32;
            const __half* g = g_wh + (size_t)(kb + r) * 256 + col0 + cb * 8;
            cp16(bS + SWZ((uint32_t)(r * 128 + cb * 16)), g, 16);
        }
    };

    issue(0, 0);
    asm volatile("cp.async.commit_group;");
    issue(1, 1);
    asm volatile("cp.async.commit_group;");

    int s = 0;
    for (int iter = 0; iter < NITER; ++iter) {
        asm volatile("cp.async.wait_group 1;");
        __syncthreads();

        if (iter + 2 < NITER) {
            int sn = (s + 2 >= 3) ? s - 1 : s + 2;
            issue(sn, iter + 2);
        }
        asm volatile("cp.async.commit_group;");

        uint32_t aS = base + (uint32_t)s * STG_B;
        uint32_t bS = aS + ASTG_B;
        #pragma unroll
        for (int kc = 0; kc < 4; ++kc) {
            uint32_t a[2][4], b[2][4];
            #pragma unroll
            for (int mi = 0; mi < 2; ++mi) {
                uint32_t off = (uint32_t)((wm + mi * 16 + (lane & 15)) * 128
                                          + kc * 32 + (lane >> 4) * 16);
                ldsm_x4(a[mi], aS + SWZ(off));
            }
            #pragma unroll
            for (int bi = 0; bi < 2; ++bi) {
                uint32_t off = (uint32_t)((kc * 16 + (lane & 15)) * 128
                                          + wn * 2 + bi * 32 + (lane >> 4) * 16);
                ldsm_x4_t(b[bi], bS + SWZ(off));
            }
            #pragma unroll
            for (int mi = 0; mi < 2; ++mi)
                #pragma unroll
                for (int ni = 0; ni < 4; ++ni) {
                    uint32_t b0 = b[ni >> 1][(ni & 1) * 2];
                    uint32_t b1 = b[ni >> 1][(ni & 1) * 2 + 1];
                    asm volatile(
                        "mma.sync.aligned.m16n8k16.row.col.f32.f16.f16.f32 "
                        "{%0,%1,%2,%3}, {%4,%5,%6,%7}, {%8,%9}, {%0,%1,%2,%3};"
                        : "+f"(acc[mi][ni][0]), "+f"(acc[mi][ni][1]),
                          "+f"(acc[mi][ni][2]), "+f"(acc[mi][ni][3])
                        : "r"(a[mi][0]), "r"(a[mi][1]), "r"(a[mi][2]), "r"(a[mi][3]),
                          "r"(b0), "r"(b1));
                }
        }
        s = (s + 1 >= 3) ? 0 : s + 1;
    }

    // Epilogue: bias hoisted (8 loads, reused across all rows).
    int g = lane >> 2, t = lane & 3;
    float bb[4][2];
    #pragma unroll
    for (int ni = 0; ni < 4; ++ni) {
        int col = col0 + wn + ni * 8 + t * 2;
        bb[ni][0] = __ldg(bias + col);
        bb[ni][1] = __ldg(bias + col + 1);
    }
    #pragma unroll
    for (int ni = 0; ni < 4; ++ni) {
        int col = col0 + wn + ni * 8 + t * 2;
        #pragma unroll
        for (int mi = 0; mi < 2; ++mi) {
            int row = row0 + wm + mi * 16 + g;
            if (row < N) {
                float2 v = make_float2(acc[mi][ni][0] + bb[ni][0],
                                       acc[mi][ni][1] + bb[ni][1]);
                *reinterpret_cast<float2*>(out + (size_t)row * 256 + col) = v;
            }
            if (row + 8 < N) {
                float2 v = make_float2(acc[mi][ni][2] + bb[ni][0],
                                       acc[mi][ni][3] + bb[ni][1]);
                *reinterpret_cast<float2*>(out + (size_t)(row + 8) * 256 + col) = v;
            }
        }
    }
}

// ---------------------------------------------------------------------------
extern "C" void kernel_launch(void* const* d_in, const int* in_sizes, int n_in,
                              void* d_out, int out_size) {
    const float* x    = (const float*)d_in[0];
    const int*   erow = (const int*)  d_in[1];
    const int*   ecol = (const int*)  d_in[2];
    const float* ew   = (const float*)d_in[3];
    const float* wgt  = (const float*)d_in[4];
    const float* bias = (const float*)d_in[5];
    float* out = (float*)d_out;

    int N = in_sizes[0] / F;   // 50000
    int E = in_sizes[1];       // 1600000

    static int once = 0;
    if (!once) {
        cudaFuncSetAttribute(gemm_h_kernel,
                             cudaFuncAttributeMaxDynamicSharedMemorySize,
                             3 * STG_B);
        once = 1;
    }

    int XB = (N * F / 4 + 1023) / 1024;          // 782 (4 float4/thread)
    int WB = (KW * F * F / 4 + 1023) / 1024;     // 48
    int RB = (N + 1 + 255) / 256;                // 196
    prep_kernel<<<XB + WB + RB, 256>>>(x, wgt, erow, E, N, XB, WB);

    spmm_h_kernel<0><<<(N + 7) / 8, 256>>>(ecol, ew);   // T1 = L xh
    spmm_h_kernel<1><<<(N + 7) / 8, 256>>>(ecol, ew);   // U  = L T1

    dim3 grid(F / GBN, (N + GBM - 1) / GBM);            // (4, 391)
    gemm_h_kernel<<<grid, 256, 3 * STG_B>>>(bias, out, N);
}